// round 3
// baseline (speedup 1.0000x reference)
#include <cuda_runtime.h>

#define N_NODES 100000
#define N_EDGES 1000000
#define IN_CH 166
#define HID 128

// ---------------- scratch (static device globals; no runtime alloc) ----------
// float4-typed to guarantee 16B alignment for vector atomics / vector loads.
__device__ float4 g_y[N_NODES * (HID / 4)];    // h @ W_l (aggregation source)
__device__ float4 g_z[N_NODES * (HID / 4)];    // h @ W_r (self term)
__device__ float4 g_agg[N_NODES * (HID / 4)];  // scatter target
__device__ float4 g_h[N_NODES * (HID / 4)];    // layer output / next input
__device__ float  g_inv[N_NODES];
__device__ float  g_deg[N_NODES];
__device__ int    g_src[N_EDGES];
__device__ int    g_dst[N_EDGES];
__device__ float2 g_y2[N_NODES];
__device__ float2 g_z2[N_NODES];
__device__ float2 g_agg2[N_NODES];

// ---------------- small utility kernels --------------------------------------
__global__ __launch_bounds__(256) void k_zero_small() {
    int i = blockIdx.x * blockDim.x + threadIdx.x;
    if (i < N_NODES) {
        g_deg[i] = 0.f;
        g_agg2[i] = make_float2(0.f, 0.f);
    }
}

__global__ __launch_bounds__(256) void k_zero_agg() {
    int i = blockIdx.x * blockDim.x + threadIdx.x;
    if (i < N_NODES * (HID / 4)) g_agg[i] = make_float4(0.f, 0.f, 0.f, 0.f);
}

// edge_index is int32 (JAX x64 disabled: jnp.int64 request silently yields int32)
__global__ __launch_bounds__(256) void k_prep(const int* __restrict__ ei) {
    int e = blockIdx.x * blockDim.x + threadIdx.x;
    if (e >= N_EDGES) return;
    int s = ei[e];
    int d = ei[N_EDGES + e];
    g_src[e] = s;
    g_dst[e] = d;
    atomicAdd(&g_deg[d], 1.0f);
}

__global__ __launch_bounds__(256) void k_inv() {
    int i = blockIdx.x * blockDim.x + threadIdx.x;
    if (i < N_NODES) g_inv[i] = 1.0f / fmaxf(g_deg[i], 1.0f);
}

// ---------------- fp32 SGEMM: C[M,128] = A[M,K] @ W[K,128] -------------------
// BM=128, BN=128, BK=8, TM=TN=8, 256 threads.
// A_IS_H: read input from g_h instead of the external pointer.
// CSEL: 0 -> g_y, 1 -> g_z.
template <int K, bool A_IS_H, int CSEL>
__global__ __launch_bounds__(256) void sgemm_nn128(const float* __restrict__ Aext,
                                                   const float* __restrict__ W, int M) {
    const float* __restrict__ A = A_IS_H ? (const float*)g_h : Aext;
    float4* __restrict__ C = (CSEL == 0) ? g_y : g_z;

    __shared__ float As[8][128];
    __shared__ float Bs[8][128];
    const int block_row = blockIdx.x * 128;
    const int tid = threadIdx.x;
    const int tr = (tid / 16) * 8;   // 0..120
    const int tc = (tid % 16) * 8;   // 0..120

    float acc[8][8];
#pragma unroll
    for (int i = 0; i < 8; i++)
#pragma unroll
        for (int j = 0; j < 8; j++) acc[i][j] = 0.f;

    for (int k0 = 0; k0 < K; k0 += 8) {
#pragma unroll
        for (int i = tid; i < 1024; i += 256) {
            int m = i >> 3, kk = i & 7;
            int row = block_row + m, col = k0 + kk;
            As[kk][m] = (row < M && col < K) ? A[row * K + col] : 0.f;
        }
#pragma unroll
        for (int i = tid; i < 1024; i += 256) {
            int kk = i >> 7, n = i & 127;
            int col = k0 + kk;
            Bs[kk][n] = (col < K) ? W[col * 128 + n] : 0.f;
        }
        __syncthreads();
#pragma unroll
        for (int kk = 0; kk < 8; kk++) {
            float a[8], b[8];
            float4 a0 = *(const float4*)&As[kk][tr];
            float4 a1 = *(const float4*)&As[kk][tr + 4];
            float4 b0 = *(const float4*)&Bs[kk][tc];
            float4 b1 = *(const float4*)&Bs[kk][tc + 4];
            a[0] = a0.x; a[1] = a0.y; a[2] = a0.z; a[3] = a0.w;
            a[4] = a1.x; a[5] = a1.y; a[6] = a1.z; a[7] = a1.w;
            b[0] = b0.x; b[1] = b0.y; b[2] = b0.z; b[3] = b0.w;
            b[4] = b1.x; b[5] = b1.y; b[6] = b1.z; b[7] = b1.w;
#pragma unroll
            for (int i = 0; i < 8; i++)
#pragma unroll
                for (int j = 0; j < 8; j++) acc[i][j] += a[i] * b[j];
        }
        __syncthreads();
    }
#pragma unroll
    for (int i = 0; i < 8; i++) {
        int row = block_row + tr + i;
        if (row < M) {
            C[row * 32 + (tc >> 2)]     = make_float4(acc[i][0], acc[i][1], acc[i][2], acc[i][3]);
            C[row * 32 + (tc >> 2) + 1] = make_float4(acc[i][4], acc[i][5], acc[i][6], acc[i][7]);
        }
    }
}

// ---------------- edge scatter: agg[dst] += y[src], 128 ch -------------------
// one warp per edge; lane holds one float4 (32 lanes * 4 = 128 floats)
__global__ __launch_bounds__(256) void k_scatter128() {
    int gt = blockIdx.x * blockDim.x + threadIdx.x;
    int e = gt >> 5;
    int lane = gt & 31;
    if (e >= N_EDGES) return;
    int s = g_src[e], d = g_dst[e];
    float4 v = g_y[s * 32 + lane];
    atomicAdd(&g_agg[d * 32 + lane], v);   // RED.E.ADD.F32x4 (result unused)
}

// ---------------- h = relu(agg*inv + z + bias) --------------------------------
__global__ __launch_bounds__(256) void k_finalize128(const float* __restrict__ bias) {
    int i = blockIdx.x * blockDim.x + threadIdx.x;
    if (i >= N_NODES * (HID / 4)) return;
    int node = i >> 5;
    int c4 = i & 31;
    float inv = g_inv[node];
    float4 a = g_agg[i];
    float4 z = g_z[i];
    float4 b = ((const float4*)bias)[c4];
    float4 r;
    r.x = fmaxf(a.x * inv + z.x + b.x, 0.f);
    r.y = fmaxf(a.y * inv + z.y + b.y, 0.f);
    r.z = fmaxf(a.z * inv + z.z + b.z, 0.f);
    r.w = fmaxf(a.w * inv + z.w + b.w, 0.f);
    g_h[i] = r;
}

// ---------------- layer-2 projection: y2 = h@W_l2, z2 = h@W_r2 ---------------
// one warp per node, warp-reduce dot products (K=128, OUT=2)
__global__ __launch_bounds__(256) void k_head(const float* __restrict__ Wl,
                                              const float* __restrict__ Wr) {
    int gt = blockIdx.x * blockDim.x + threadIdx.x;
    int node = gt >> 5;
    int lane = gt & 31;
    if (node >= N_NODES) return;
    float4 v = g_h[node * 32 + lane];
    float hv[4] = {v.x, v.y, v.z, v.w};
    float l0 = 0.f, l1 = 0.f, r0 = 0.f, r1 = 0.f;
#pragma unroll
    for (int j = 0; j < 4; j++) {
        int k = lane * 4 + j;
        l0 += hv[j] * __ldg(&Wl[k * 2 + 0]);
        l1 += hv[j] * __ldg(&Wl[k * 2 + 1]);
        r0 += hv[j] * __ldg(&Wr[k * 2 + 0]);
        r1 += hv[j] * __ldg(&Wr[k * 2 + 1]);
    }
#pragma unroll
    for (int off = 16; off; off >>= 1) {
        l0 += __shfl_xor_sync(0xffffffffu, l0, off);
        l1 += __shfl_xor_sync(0xffffffffu, l1, off);
        r0 += __shfl_xor_sync(0xffffffffu, r0, off);
        r1 += __shfl_xor_sync(0xffffffffu, r1, off);
    }
    if (lane == 0) {
        g_y2[node] = make_float2(l0, l1);
        g_z2[node] = make_float2(r0, r1);
    }
}

// ---------------- layer-2 scatter (2 channels per edge) ----------------------
__global__ __launch_bounds__(256) void k_scatter2() {
    int e = blockIdx.x * blockDim.x + threadIdx.x;
    if (e >= N_EDGES) return;
    int s = g_src[e], d = g_dst[e];
    float2 v = g_y2[s];
    atomicAdd(&g_agg2[d], v);   // RED.E.ADD.F32x2
}

__global__ __launch_bounds__(256) void k_finalize2(const float* __restrict__ bias,
                                                   float* __restrict__ out) {
    int i = blockIdx.x * blockDim.x + threadIdx.x;
    if (i >= N_NODES) return;
    float inv = g_inv[i];
    float2 a = g_agg2[i];
    float2 z = g_z2[i];
    out[i * 2 + 0] = a.x * inv + z.x + bias[0];
    out[i * 2 + 1] = a.y * inv + z.y + bias[1];
}

// ---------------- launch ------------------------------------------------------
extern "C" void kernel_launch(void* const* d_in, const int* in_sizes, int n_in,
                              void* d_out, int out_size) {
    const float* x    = (const float*)d_in[0];
    const int*   ei   = (const int*)d_in[1];     // int32! (JAX x64 disabled)
    const float* Wl0  = (const float*)d_in[2];
    const float* bl0  = (const float*)d_in[3];
    const float* Wr0  = (const float*)d_in[4];
    const float* Wl1  = (const float*)d_in[5];
    const float* bl1  = (const float*)d_in[6];
    const float* Wr1  = (const float*)d_in[7];
    const float* Wl2  = (const float*)d_in[8];
    const float* bl2  = (const float*)d_in[9];
    const float* Wr2  = (const float*)d_in[10];
    float*       out  = (float*)d_out;

    const int M = N_NODES;
    const int GEMM_BLOCKS = (M + 127) / 128;            // 782
    const int AGG4 = N_NODES * (HID / 4);               // 3.2e6

    // degree + edge prep
    k_zero_small<<<(N_NODES + 255) / 256, 256>>>();
    k_prep<<<(N_EDGES + 255) / 256, 256>>>(ei);
    k_inv<<<(N_NODES + 255) / 256, 256>>>();

    // -------- layer 0 --------
    k_zero_agg<<<(AGG4 + 255) / 256, 256>>>();
    sgemm_nn128<IN_CH, false, 0><<<GEMM_BLOCKS, 256>>>(x, Wl0, M);
    sgemm_nn128<IN_CH, false, 1><<<GEMM_BLOCKS, 256>>>(x, Wr0, M);
    k_scatter128<<<(N_EDGES * 32) / 256, 256>>>();
    k_finalize128<<<(AGG4 + 255) / 256, 256>>>(bl0);

    // -------- layer 1 --------
    k_zero_agg<<<(AGG4 + 255) / 256, 256>>>();
    sgemm_nn128<HID, true, 0><<<GEMM_BLOCKS, 256>>>(nullptr, Wl1, M);
    sgemm_nn128<HID, true, 1><<<GEMM_BLOCKS, 256>>>(nullptr, Wr1, M);
    k_scatter128<<<(N_EDGES * 32) / 256, 256>>>();
    k_finalize128<<<(AGG4 + 255) / 256, 256>>>(bl1);

    // -------- layer 2 (project to 2 dims BEFORE aggregating) --------
    k_head<<<(N_NODES * 32 + 255) / 256, 256>>>(Wl2, Wr2);
    k_scatter2<<<(N_EDGES + 255) / 256, 256>>>();
    k_finalize2<<<(N_NODES + 255) / 256, 256>>>(bl2, out);
}

// round 4
// speedup vs baseline: 1.5099x; 1.5099x over previous
#include <cuda_runtime.h>
#include <cuda_bf16.h>
#include <cstdint>

#define N_NODES 100000
#define N_EDGES 1000000
#define IN_CH 166
#define HID 128
#define KPAD0 192   // IN_CH padded up to multiple of 32
#define SMS 40      // smem row stride in bf16 (32 data + 8 pad -> 80B, conflict-free ldmatrix)

// ---------------- scratch (static device globals; no runtime alloc) ----------
__device__ float4 g_y[N_NODES * (HID / 4)];    // A@W_l (aggregation source)
__device__ float4 g_z[N_NODES * (HID / 4)];    // A@W_r (self term)
__device__ float4 g_agg[N_NODES * (HID / 4)];  // scatter target
__device__ float4 g_h[N_NODES * (HID / 4)];    // layer output (fp32, for k_head)
__device__ float  g_inv[N_NODES];
__device__ float  g_deg[N_NODES];
__device__ int    g_src[N_EDGES];
__device__ int    g_dst[N_EDGES];
__device__ float2 g_y2[N_NODES];
__device__ float2 g_z2[N_NODES];
__device__ float2 g_agg2[N_NODES];
// bf16x2 split operands for tensor-core GEMM
__device__ __nv_bfloat16 g_Ah[N_NODES * KPAD0];
__device__ __nv_bfloat16 g_Al[N_NODES * KPAD0];
__device__ __nv_bfloat16 g_Bh[256 * KPAD0];    // [n(0..255)][k] transposed, Wl|Wr
__device__ __nv_bfloat16 g_Bl[256 * KPAD0];

// ---------------- helpers ----------------------------------------------------
__device__ __forceinline__ uint32_t smem_u32(const void* p) {
    return (uint32_t)__cvta_generic_to_shared(p);
}
__device__ __forceinline__ void ldsm_x4(uint32_t& r0, uint32_t& r1, uint32_t& r2,
                                        uint32_t& r3, uint32_t addr) {
    asm volatile("ldmatrix.sync.aligned.m8n8.x4.shared.b16 {%0,%1,%2,%3}, [%4];"
                 : "=r"(r0), "=r"(r1), "=r"(r2), "=r"(r3) : "r"(addr));
}
__device__ __forceinline__ void mma_bf16(float* d, const uint32_t* a, uint32_t b0, uint32_t b1) {
    asm volatile(
        "mma.sync.aligned.m16n8k16.row.col.f32.bf16.bf16.f32 "
        "{%0,%1,%2,%3}, {%4,%5,%6,%7}, {%8,%9}, {%0,%1,%2,%3};"
        : "+f"(d[0]), "+f"(d[1]), "+f"(d[2]), "+f"(d[3])
        : "r"(a[0]), "r"(a[1]), "r"(a[2]), "r"(a[3]), "r"(b0), "r"(b1));
}
__device__ __forceinline__ void split2(float v, __nv_bfloat16& hi, __nv_bfloat16& lo) {
    hi = __float2bfloat16(v);
    lo = __float2bfloat16(v - __bfloat162float(hi));
}

// ---------------- small utility kernels --------------------------------------
__global__ __launch_bounds__(256) void k_zero_small() {
    int i = blockIdx.x * blockDim.x + threadIdx.x;
    if (i < N_NODES) {
        g_deg[i] = 0.f;
        g_agg2[i] = make_float2(0.f, 0.f);
    }
}

__global__ __launch_bounds__(256) void k_zero_agg() {
    int i = blockIdx.x * blockDim.x + threadIdx.x;
    if (i < N_NODES * (HID / 4)) g_agg[i] = make_float4(0.f, 0.f, 0.f, 0.f);
}

// edge_index is int32 (JAX x64 disabled)
__global__ __launch_bounds__(256) void k_prep(const int* __restrict__ ei) {
    int e = blockIdx.x * blockDim.x + threadIdx.x;
    if (e >= N_EDGES) return;
    int s = ei[e];
    int d = ei[N_EDGES + e];
    g_src[e] = s;
    g_dst[e] = d;
    atomicAdd(&g_deg[d], 1.0f);
}

__global__ __launch_bounds__(256) void k_inv() {
    int i = blockIdx.x * blockDim.x + threadIdx.x;
    if (i < N_NODES) g_inv[i] = 1.0f / fmaxf(g_deg[i], 1.0f);
}

// split x[N,166] -> g_Ah/g_Al [N,192] (zero padded)
__global__ __launch_bounds__(256) void k_split_x(const float* __restrict__ x) {
    int i = blockIdx.x * blockDim.x + threadIdx.x;
    if (i >= N_NODES * KPAD0) return;
    int m = i / KPAD0, c = i - m * KPAD0;
    float v = (c < IN_CH) ? x[m * IN_CH + c] : 0.f;
    __nv_bfloat16 hi, lo;
    split2(v, hi, lo);
    g_Ah[i] = hi;
    g_Al[i] = lo;
}

// split + transpose weights: g_Bh/g_Bl[n][k], n<128 from Wl, n>=128 from Wr
__global__ __launch_bounds__(256) void k_split_w(const float* __restrict__ Wl,
                                                 const float* __restrict__ Wr,
                                                 int K, int KP) {
    int i = blockIdx.x * blockDim.x + threadIdx.x;
    if (i >= 256 * KP) return;
    int n = i / KP, k = i - n * KP;
    float v = 0.f;
    if (k < K) v = (n < 128) ? Wl[k * 128 + n] : Wr[k * 128 + (n - 128)];
    __nv_bfloat16 hi, lo;
    split2(v, hi, lo);
    g_Bh[i] = hi;
    g_Bl[i] = lo;
}

// ---------------- bf16x3 tensor-core GEMM ------------------------------------
// C[M,128] = A[M,K] @ W[K,128] with A in split bf16 (g_Ah/g_Al, stride KPAD)
// and W in split transposed bf16 (g_Bh/g_Bl, [256][KPAD]).
// blockIdx.y: 0 -> Wl half -> g_y ; 1 -> Wr half -> g_z.
// BM=128, BN=128, BK=32; 8 warps as 4(M) x 2(N); warp tile 32x64.
template <int KPAD>
__global__ __launch_bounds__(256) void tc_gemm(int M) {
    __shared__ __nv_bfloat16 Ah_s[128 * SMS];
    __shared__ __nv_bfloat16 Al_s[128 * SMS];
    __shared__ __nv_bfloat16 Bh_s[128 * SMS];
    __shared__ __nv_bfloat16 Bl_s[128 * SMS];

    const int tid = threadIdx.x;
    const int lane = tid & 31;
    const int wid = tid >> 5;
    const int warpM = wid >> 1;          // 0..3
    const int warpN = wid & 1;           // 0..1
    const int m0 = blockIdx.x * 128;
    const int by = blockIdx.y;

    const __nv_bfloat16* __restrict__ Bgh = g_Bh + by * 128 * KPAD;
    const __nv_bfloat16* __restrict__ Bgl = g_Bl + by * 128 * KPAD;

    float acc[2][8][4];
#pragma unroll
    for (int a = 0; a < 2; a++)
#pragma unroll
        for (int b = 0; b < 8; b++)
#pragma unroll
            for (int c = 0; c < 4; c++) acc[a][b][c] = 0.f;

    const int srow = tid >> 1;            // 0..127
    const int shalf = (tid & 1) * 16;     // bf16 offset 0 or 16

    for (int k0 = 0; k0 < KPAD; k0 += 32) {
        // ---- stage tiles (16B vector copies) ----
        {
            const bool valid = (m0 + srow) < M;
            const size_t aoff = (size_t)(m0 + srow) * KPAD + k0 + shalf;
            uint4 z = {0u, 0u, 0u, 0u};
            uint4 vh0 = z, vh1 = z, vl0 = z, vl1 = z;
            if (valid) {
                vh0 = *(const uint4*)(g_Ah + aoff);
                vh1 = *(const uint4*)(g_Ah + aoff + 8);
                vl0 = *(const uint4*)(g_Al + aoff);
                vl1 = *(const uint4*)(g_Al + aoff + 8);
            }
            int so = srow * SMS + shalf;
            *(uint4*)(Ah_s + so) = vh0;
            *(uint4*)(Ah_s + so + 8) = vh1;
            *(uint4*)(Al_s + so) = vl0;
            *(uint4*)(Al_s + so + 8) = vl1;

            const size_t boff = (size_t)srow * KPAD + k0 + shalf;
            uint4 wh0 = *(const uint4*)(Bgh + boff);
            uint4 wh1 = *(const uint4*)(Bgh + boff + 8);
            uint4 wl0 = *(const uint4*)(Bgl + boff);
            uint4 wl1 = *(const uint4*)(Bgl + boff + 8);
            *(uint4*)(Bh_s + so) = wh0;
            *(uint4*)(Bh_s + so + 8) = wh1;
            *(uint4*)(Bl_s + so) = wl0;
            *(uint4*)(Bl_s + so + 8) = wl1;
        }
        __syncthreads();

#pragma unroll
        for (int kk = 0; kk < 32; kk += 16) {
            // A fragments (2 m16 tiles, hi+lo)
            uint32_t ah[2][4], al[2][4];
#pragma unroll
            for (int mt = 0; mt < 2; mt++) {
                int r = warpM * 32 + mt * 16 + (lane & 15);
                int c = kk + ((lane >> 4) << 3);
                uint32_t ad = smem_u32(Ah_s + r * SMS + c);
                ldsm_x4(ah[mt][0], ah[mt][1], ah[mt][2], ah[mt][3], ad);
                uint32_t ad2 = smem_u32(Al_s + r * SMS + c);
                ldsm_x4(al[mt][0], al[mt][1], al[mt][2], al[mt][3], ad2);
            }
            // B fragments: 4 groups of n16
#pragma unroll
            for (int g = 0; g < 4; g++) {
                int nrow = warpN * 64 + g * 16 + (lane & 7) + ((lane >> 4) << 3);
                int kc = kk + (((lane >> 3) & 1) << 3);
                uint32_t bd = smem_u32(Bh_s + nrow * SMS + kc);
                uint32_t bh0, bh1, bh2, bh3;
                ldsm_x4(bh0, bh1, bh2, bh3, bd);
                uint32_t bd2 = smem_u32(Bl_s + nrow * SMS + kc);
                uint32_t bl0, bl1, bl2, bl3;
                ldsm_x4(bl0, bl1, bl2, bl3, bd2);
#pragma unroll
                for (int mt = 0; mt < 2; mt++) {
                    mma_bf16(acc[mt][g * 2],     ah[mt], bh0, bh1);
                    mma_bf16(acc[mt][g * 2],     ah[mt], bl0, bl1);
                    mma_bf16(acc[mt][g * 2],     al[mt], bh0, bh1);
                    mma_bf16(acc[mt][g * 2 + 1], ah[mt], bh2, bh3);
                    mma_bf16(acc[mt][g * 2 + 1], ah[mt], bl2, bl3);
                    mma_bf16(acc[mt][g * 2 + 1], al[mt], bh2, bh3);
                }
            }
        }
        __syncthreads();
    }

    // ---- store C (fp32, float2 per fragment row) ----
    float* Cb = (by == 0) ? (float*)g_y : (float*)g_z;
#pragma unroll
    for (int mt = 0; mt < 2; mt++) {
#pragma unroll
        for (int j = 0; j < 8; j++) {
            int row = m0 + warpM * 32 + mt * 16 + (lane >> 2);
            int col = warpN * 64 + j * 8 + 2 * (lane & 3);
            if (row < M)
                *(float2*)&Cb[(size_t)row * 128 + col] = make_float2(acc[mt][j][0], acc[mt][j][1]);
            if (row + 8 < M)
                *(float2*)&Cb[(size_t)(row + 8) * 128 + col] = make_float2(acc[mt][j][2], acc[mt][j][3]);
        }
    }
}

// ---------------- edge scatter: agg[dst] += y[src], 128 ch -------------------
__global__ __launch_bounds__(256) void k_scatter128() {
    int gt = blockIdx.x * blockDim.x + threadIdx.x;
    int e = gt >> 5;
    int lane = gt & 31;
    if (e >= N_EDGES) return;
    int s = g_src[e], d = g_dst[e];
    float4 v = g_y[s * 32 + lane];
    atomicAdd(&g_agg[d * 32 + lane], v);   // RED.E.ADD.F32x4
}

// ---------------- h = relu(agg*inv + z + bias); optionally write bf16 split --
template <bool WRITE_SPLIT>
__global__ __launch_bounds__(256) void k_finalize128(const float* __restrict__ bias) {
    int i = blockIdx.x * blockDim.x + threadIdx.x;
    if (i >= N_NODES * (HID / 4)) return;
    int node = i >> 5;
    int c4 = i & 31;
    float inv = g_inv[node];
    float4 a = g_agg[i];
    float4 z = g_z[i];
    float4 b = ((const float4*)bias)[c4];
    float4 r;
    r.x = fmaxf(a.x * inv + z.x + b.x, 0.f);
    r.y = fmaxf(a.y * inv + z.y + b.y, 0.f);
    r.z = fmaxf(a.z * inv + z.z + b.z, 0.f);
    r.w = fmaxf(a.w * inv + z.w + b.w, 0.f);
    g_h[i] = r;
    if (WRITE_SPLIT) {
        // layer-1 GEMM reads g_Ah/g_Al with stride 128
        int base = node * 128 + c4 * 4;
        __nv_bfloat16 h0, l0, h1, l1, h2, l2, h3, l3;
        split2(r.x, h0, l0);
        split2(r.y, h1, l1);
        split2(r.z, h2, l2);
        split2(r.w, h3, l3);
        *(__nv_bfloat162*)(g_Ah + base)     = __nv_bfloat162(h0, h1);
        *(__nv_bfloat162*)(g_Ah + base + 2) = __nv_bfloat162(h2, h3);
        *(__nv_bfloat162*)(g_Al + base)     = __nv_bfloat162(l0, l1);
        *(__nv_bfloat162*)(g_Al + base + 2) = __nv_bfloat162(l2, l3);
    }
}

// ---------------- layer-2 projection: y2 = h@W_l2, z2 = h@W_r2 ---------------
__global__ __launch_bounds__(256) void k_head(const float* __restrict__ Wl,
                                              const float* __restrict__ Wr) {
    int gt = blockIdx.x * blockDim.x + threadIdx.x;
    int node = gt >> 5;
    int lane = gt & 31;
    if (node >= N_NODES) return;
    float4 v = g_h[node * 32 + lane];
    float hv[4] = {v.x, v.y, v.z, v.w};
    float l0 = 0.f, l1 = 0.f, r0 = 0.f, r1 = 0.f;
#pragma unroll
    for (int j = 0; j < 4; j++) {
        int k = lane * 4 + j;
        l0 += hv[j] * __ldg(&Wl[k * 2 + 0]);
        l1 += hv[j] * __ldg(&Wl[k * 2 + 1]);
        r0 += hv[j] * __ldg(&Wr[k * 2 + 0]);
        r1 += hv[j] * __ldg(&Wr[k * 2 + 1]);
    }
#pragma unroll
    for (int off = 16; off; off >>= 1) {
        l0 += __shfl_xor_sync(0xffffffffu, l0, off);
        l1 += __shfl_xor_sync(0xffffffffu, l1, off);
        r0 += __shfl_xor_sync(0xffffffffu, r0, off);
        r1 += __shfl_xor_sync(0xffffffffu, r1, off);
    }
    if (lane == 0) {
        g_y2[node] = make_float2(l0, l1);
        g_z2[node] = make_float2(r0, r1);
    }
}

__global__ __launch_bounds__(256) void k_scatter2() {
    int e = blockIdx.x * blockDim.x + threadIdx.x;
    if (e >= N_EDGES) return;
    int s = g_src[e], d = g_dst[e];
    float2 v = g_y2[s];
    atomicAdd(&g_agg2[d], v);
}

__global__ __launch_bounds__(256) void k_finalize2(const float* __restrict__ bias,
                                                   float* __restrict__ out) {
    int i = blockIdx.x * blockDim.x + threadIdx.x;
    if (i >= N_NODES) return;
    float inv = g_inv[i];
    float2 a = g_agg2[i];
    float2 z = g_z2[i];
    out[i * 2 + 0] = a.x * inv + z.x + bias[0];
    out[i * 2 + 1] = a.y * inv + z.y + bias[1];
}

// ---------------- launch ------------------------------------------------------
extern "C" void kernel_launch(void* const* d_in, const int* in_sizes, int n_in,
                              void* d_out, int out_size) {
    const float* x    = (const float*)d_in[0];
    const int*   ei   = (const int*)d_in[1];     // int32 (JAX x64 disabled)
    const float* Wl0  = (const float*)d_in[2];
    const float* bl0  = (const float*)d_in[3];
    const float* Wr0  = (const float*)d_in[4];
    const float* Wl1  = (const float*)d_in[5];
    const float* bl1  = (const float*)d_in[6];
    const float* Wr1  = (const float*)d_in[7];
    const float* Wl2  = (const float*)d_in[8];
    const float* bl2  = (const float*)d_in[9];
    const float* Wr2  = (const float*)d_in[10];
    float*       out  = (float*)d_out;

    const int M = N_NODES;
    const int AGG4 = N_NODES * (HID / 4);
    dim3 gemm_grid((M + 127) / 128, 2);

    // degree + edge prep
    k_zero_small<<<(N_NODES + 255) / 256, 256>>>();
    k_prep<<<(N_EDGES + 255) / 256, 256>>>(ei);
    k_inv<<<(N_NODES + 255) / 256, 256>>>();

    // -------- layer 0 --------
    k_split_x<<<(N_NODES * KPAD0 + 255) / 256, 256>>>(x);
    k_split_w<<<(256 * KPAD0 + 255) / 256, 256>>>(Wl0, Wr0, IN_CH, KPAD0);
    k_zero_agg<<<(AGG4 + 255) / 256, 256>>>();
    tc_gemm<KPAD0><<<gemm_grid, 256>>>(M);
    k_scatter128<<<(N_EDGES * 32) / 256, 256>>>();
    k_finalize128<true><<<(AGG4 + 255) / 256, 256>>>(bl0);

    // -------- layer 1 --------
    k_split_w<<<(256 * HID + 255) / 256, 256>>>(Wl1, Wr1, HID, HID);
    k_zero_agg<<<(AGG4 + 255) / 256, 256>>>();
    tc_gemm<HID><<<gemm_grid, 256>>>(M);
    k_scatter128<<<(N_EDGES * 32) / 256, 256>>>();
    k_finalize128<false><<<(AGG4 + 255) / 256, 256>>>(bl1);

    // -------- layer 2 (project to 2 dims BEFORE aggregating) --------
    k_head<<<(N_NODES * 32 + 255) / 256, 256>>>(Wl2, Wr2);
    k_scatter2<<<(N_EDGES + 255) / 256, 256>>>();
    k_finalize2<<<(N_NODES + 255) / 256, 256>>>(bl2, out);
}

// round 5
// speedup vs baseline: 2.1378x; 1.4158x over previous
#include <cuda_runtime.h>
#include <cuda_bf16.h>
#include <cstdint>

#define N_NODES 100000
#define N_EDGES 1000000
#define IN_CH 166
#define HID 128
#define KPAD0 192   // IN_CH padded up to multiple of 32
#define SMS 40      // smem row stride in bf16 (80B, conflict-free ldmatrix)
#define NB ((N_NODES + 255) / 256)   // 391 scan blocks

// ---------------- scratch (static device globals; no runtime alloc) ----------
__device__ float4 g_y[N_NODES * (HID / 4)];    // A@W_l (aggregation source)
__device__ float4 g_z[N_NODES * (HID / 4)];    // A@W_r (self term)
__device__ float4 g_h[N_NODES * (HID / 4)];    // layer output (fp32, for k_head)
__device__ float2 g_y2[N_NODES];
__device__ float2 g_z2[N_NODES];
// CSR by destination
__device__ int g_degi[N_NODES];
__device__ int g_lex[N_NODES];        // local exclusive scan
__device__ int g_bsum[NB];
__device__ int g_boff[NB];
__device__ int g_rowstart[N_NODES + 1];
__device__ int g_cursor[N_NODES];
__device__ int g_csr[N_EDGES];        // src per edge, grouped by dst
// bf16x2 split operands for tensor-core GEMM
__device__ __nv_bfloat16 g_Ah[N_NODES * KPAD0];
__device__ __nv_bfloat16 g_Al[N_NODES * KPAD0];
__device__ __nv_bfloat16 g_Bh[256 * KPAD0];    // [n][k] transposed, Wl|Wr halves
__device__ __nv_bfloat16 g_Bl[256 * KPAD0];

// ---------------- helpers ----------------------------------------------------
__device__ __forceinline__ uint32_t smem_u32(const void* p) {
    return (uint32_t)__cvta_generic_to_shared(p);
}
__device__ __forceinline__ void ldsm_x4(uint32_t& r0, uint32_t& r1, uint32_t& r2,
                                        uint32_t& r3, uint32_t addr) {
    asm volatile("ldmatrix.sync.aligned.m8n8.x4.shared.b16 {%0,%1,%2,%3}, [%4];"
                 : "=r"(r0), "=r"(r1), "=r"(r2), "=r"(r3) : "r"(addr));
}
__device__ __forceinline__ void mma_bf16(float* d, const uint32_t* a, uint32_t b0, uint32_t b1) {
    asm volatile(
        "mma.sync.aligned.m16n8k16.row.col.f32.bf16.bf16.f32 "
        "{%0,%1,%2,%3}, {%4,%5,%6,%7}, {%8,%9}, {%0,%1,%2,%3};"
        : "+f"(d[0]), "+f"(d[1]), "+f"(d[2]), "+f"(d[3])
        : "r"(a[0]), "r"(a[1]), "r"(a[2]), "r"(a[3]), "r"(b0), "r"(b1));
}
__device__ __forceinline__ void split2(float v, __nv_bfloat16& hi, __nv_bfloat16& lo) {
    hi = __float2bfloat16(v);
    lo = __float2bfloat16(v - __bfloat162float(hi));
}

// ---------------- CSR build ---------------------------------------------------
__global__ __launch_bounds__(256) void k_zero_degi() {
    int i = blockIdx.x * blockDim.x + threadIdx.x;
    if (i < N_NODES) g_degi[i] = 0;
}

// edge_index is int32 (JAX x64 disabled)
__global__ __launch_bounds__(256) void k_hist(const int* __restrict__ ei) {
    int e = blockIdx.x * blockDim.x + threadIdx.x;
    if (e >= N_EDGES) return;
    atomicAdd(&g_degi[ei[N_EDGES + e]], 1);
}

__global__ __launch_bounds__(256) void k_scan_block() {
    __shared__ int s[256];
    int i = blockIdx.x * 256 + threadIdx.x;
    int t = threadIdx.x;
    int v = (i < N_NODES) ? g_degi[i] : 0;
    s[t] = v;
    __syncthreads();
#pragma unroll
    for (int off = 1; off < 256; off <<= 1) {
        int add = (t >= off) ? s[t - off] : 0;
        __syncthreads();
        s[t] += add;
        __syncthreads();
    }
    if (i < N_NODES) g_lex[i] = s[t] - v;           // exclusive
    if (t == 255) g_bsum[blockIdx.x] = s[255];      // block total
}

__global__ __launch_bounds__(512) void k_scan_top() {
    __shared__ int s[512];
    int t = threadIdx.x;
    int v = (t < NB) ? g_bsum[t] : 0;
    s[t] = v;
    __syncthreads();
#pragma unroll
    for (int off = 1; off < 512; off <<= 1) {
        int add = (t >= off) ? s[t - off] : 0;
        __syncthreads();
        s[t] += add;
        __syncthreads();
    }
    if (t < NB) g_boff[t] = s[t] - v;               // exclusive
}

__global__ __launch_bounds__(256) void k_scan_fin() {
    int i = blockIdx.x * 256 + threadIdx.x;
    if (i < N_NODES) {
        int rs = g_lex[i] + g_boff[blockIdx.x];
        g_rowstart[i] = rs;
        g_cursor[i] = rs;
    }
    if (i == 0) g_rowstart[N_NODES] = N_EDGES;
}

__global__ __launch_bounds__(256) void k_fill(const int* __restrict__ ei) {
    int e = blockIdx.x * blockDim.x + threadIdx.x;
    if (e >= N_EDGES) return;
    int s = ei[e];
    int d = ei[N_EDGES + e];
    int pos = atomicAdd(&g_cursor[d], 1);
    g_csr[pos] = s;
}

// ---------------- split passes ------------------------------------------------
// thread handles 4 channels: scalar loads (row stride 166 unaligned), 8B stores
__global__ __launch_bounds__(256) void k_split_x(const float* __restrict__ x) {
    int i = blockIdx.x * blockDim.x + threadIdx.x;      // over N * 48
    if (i >= N_NODES * (KPAD0 / 4)) return;
    int m = i / (KPAD0 / 4);
    int c = (i - m * (KPAD0 / 4)) * 4;
    __nv_bfloat16 hi[4], lo[4];
#pragma unroll
    for (int j = 0; j < 4; j++) {
        float v = (c + j < IN_CH) ? __ldg(&x[(size_t)m * IN_CH + c + j]) : 0.f;
        split2(v, hi[j], lo[j]);
    }
    size_t o = (size_t)m * KPAD0 + c;
    *(__nv_bfloat162*)(g_Ah + o)     = __nv_bfloat162(hi[0], hi[1]);
    *(__nv_bfloat162*)(g_Ah + o + 2) = __nv_bfloat162(hi[2], hi[3]);
    *(__nv_bfloat162*)(g_Al + o)     = __nv_bfloat162(lo[0], lo[1]);
    *(__nv_bfloat162*)(g_Al + o + 2) = __nv_bfloat162(lo[2], lo[3]);
}

__global__ __launch_bounds__(256) void k_split_w(const float* __restrict__ Wl,
                                                 const float* __restrict__ Wr,
                                                 int K, int KP) {
    int i = blockIdx.x * blockDim.x + threadIdx.x;
    if (i >= 256 * KP) return;
    int n = i / KP, k = i - n * KP;
    float v = 0.f;
    if (k < K) v = (n < 128) ? Wl[k * 128 + n] : Wr[k * 128 + (n - 128)];
    __nv_bfloat16 hi, lo;
    split2(v, hi, lo);
    g_Bh[i] = hi;
    g_Bl[i] = lo;
}

// ---------------- bf16x3 tensor-core GEMM ------------------------------------
// blockIdx.y: 0 -> Wl half -> g_y ; 1 -> Wr half -> g_z.
template <int KPAD>
__global__ __launch_bounds__(256) void tc_gemm(int M) {
    __shared__ __nv_bfloat16 Ah_s[128 * SMS];
    __shared__ __nv_bfloat16 Al_s[128 * SMS];
    __shared__ __nv_bfloat16 Bh_s[128 * SMS];
    __shared__ __nv_bfloat16 Bl_s[128 * SMS];

    const int tid = threadIdx.x;
    const int lane = tid & 31;
    const int wid = tid >> 5;
    const int warpM = wid >> 1;
    const int warpN = wid & 1;
    const int m0 = blockIdx.x * 128;
    const int by = blockIdx.y;

    const __nv_bfloat16* __restrict__ Bgh = g_Bh + by * 128 * KPAD;
    const __nv_bfloat16* __restrict__ Bgl = g_Bl + by * 128 * KPAD;

    float acc[2][8][4];
#pragma unroll
    for (int a = 0; a < 2; a++)
#pragma unroll
        for (int b = 0; b < 8; b++)
#pragma unroll
            for (int c = 0; c < 4; c++) acc[a][b][c] = 0.f;

    const int srow = tid >> 1;
    const int shalf = (tid & 1) * 16;

    for (int k0 = 0; k0 < KPAD; k0 += 32) {
        {
            const bool valid = (m0 + srow) < M;
            const size_t aoff = (size_t)(m0 + srow) * KPAD + k0 + shalf;
            uint4 zz = {0u, 0u, 0u, 0u};
            uint4 vh0 = zz, vh1 = zz, vl0 = zz, vl1 = zz;
            if (valid) {
                vh0 = *(const uint4*)(g_Ah + aoff);
                vh1 = *(const uint4*)(g_Ah + aoff + 8);
                vl0 = *(const uint4*)(g_Al + aoff);
                vl1 = *(const uint4*)(g_Al + aoff + 8);
            }
            int so = srow * SMS + shalf;
            *(uint4*)(Ah_s + so) = vh0;
            *(uint4*)(Ah_s + so + 8) = vh1;
            *(uint4*)(Al_s + so) = vl0;
            *(uint4*)(Al_s + so + 8) = vl1;

            const size_t boff = (size_t)srow * KPAD + k0 + shalf;
            uint4 wh0 = *(const uint4*)(Bgh + boff);
            uint4 wh1 = *(const uint4*)(Bgh + boff + 8);
            uint4 wl0 = *(const uint4*)(Bgl + boff);
            uint4 wl1 = *(const uint4*)(Bgl + boff + 8);
            *(uint4*)(Bh_s + so) = wh0;
            *(uint4*)(Bh_s + so + 8) = wh1;
            *(uint4*)(Bl_s + so) = wl0;
            *(uint4*)(Bl_s + so + 8) = wl1;
        }
        __syncthreads();

#pragma unroll
        for (int kk = 0; kk < 32; kk += 16) {
            uint32_t ah[2][4], al[2][4];
#pragma unroll
            for (int mt = 0; mt < 2; mt++) {
                int r = warpM * 32 + mt * 16 + (lane & 15);
                int c = kk + ((lane >> 4) << 3);
                ldsm_x4(ah[mt][0], ah[mt][1], ah[mt][2], ah[mt][3],
                        smem_u32(Ah_s + r * SMS + c));
                ldsm_x4(al[mt][0], al[mt][1], al[mt][2], al[mt][3],
                        smem_u32(Al_s + r * SMS + c));
            }
#pragma unroll
            for (int g = 0; g < 4; g++) {
                int nrow = warpN * 64 + g * 16 + (lane & 7) + ((lane >> 4) << 3);
                int kc = kk + (((lane >> 3) & 1) << 3);
                uint32_t bh0, bh1, bh2, bh3, bl0, bl1, bl2, bl3;
                ldsm_x4(bh0, bh1, bh2, bh3, smem_u32(Bh_s + nrow * SMS + kc));
                ldsm_x4(bl0, bl1, bl2, bl3, smem_u32(Bl_s + nrow * SMS + kc));
#pragma unroll
                for (int mt = 0; mt < 2; mt++) {
                    mma_bf16(acc[mt][g * 2],     ah[mt], bh0, bh1);
                    mma_bf16(acc[mt][g * 2],     ah[mt], bl0, bl1);
                    mma_bf16(acc[mt][g * 2],     al[mt], bh0, bh1);
                    mma_bf16(acc[mt][g * 2 + 1], ah[mt], bh2, bh3);
                    mma_bf16(acc[mt][g * 2 + 1], ah[mt], bl2, bl3);
                    mma_bf16(acc[mt][g * 2 + 1], al[mt], bh2, bh3);
                }
            }
        }
        __syncthreads();
    }

    float* Cb = (by == 0) ? (float*)g_y : (float*)g_z;
#pragma unroll
    for (int mt = 0; mt < 2; mt++) {
#pragma unroll
        for (int j = 0; j < 8; j++) {
            int row = m0 + warpM * 32 + mt * 16 + (lane >> 2);
            int col = warpN * 64 + j * 8 + 2 * (lane & 3);
            if (row < M)
                *(float2*)((float*)Cb + (size_t)row * 128 + col) =
                    make_float2(acc[mt][j][0], acc[mt][j][1]);
            if (row + 8 < M)
                *(float2*)((float*)Cb + (size_t)(row + 8) * 128 + col) =
                    make_float2(acc[mt][j][2], acc[mt][j][3]);
        }
    }
}

// ---------------- fused CSR gather + mean + self + bias + relu ---------------
// warp per dst node; lane owns one float4 (4 channels); 2-way unrolled edges.
template <bool WRITE_SPLIT>
__global__ __launch_bounds__(256) void k_gather128(const float* __restrict__ bias) {
    int gt = blockIdx.x * blockDim.x + threadIdx.x;
    int node = gt >> 5;
    int lane = gt & 31;
    if (node >= N_NODES) return;
    int beg = g_rowstart[node];
    int end = g_rowstart[node + 1];
    float4 a0 = make_float4(0.f, 0.f, 0.f, 0.f);
    float4 a1 = make_float4(0.f, 0.f, 0.f, 0.f);
    int e = beg;
    for (; e + 1 < end; e += 2) {
        int s0 = g_csr[e], s1 = g_csr[e + 1];
        float4 v0 = g_y[s0 * 32 + lane];
        float4 v1 = g_y[s1 * 32 + lane];
        a0.x += v0.x; a0.y += v0.y; a0.z += v0.z; a0.w += v0.w;
        a1.x += v1.x; a1.y += v1.y; a1.z += v1.z; a1.w += v1.w;
    }
    if (e < end) {
        float4 v0 = g_y[g_csr[e] * 32 + lane];
        a0.x += v0.x; a0.y += v0.y; a0.z += v0.z; a0.w += v0.w;
    }
    float inv = 1.0f / fmaxf((float)(end - beg), 1.0f);
    float4 z = g_z[node * 32 + lane];
    float4 b = ((const float4*)bias)[lane];
    float4 r;
    r.x = fmaxf((a0.x + a1.x) * inv + z.x + b.x, 0.f);
    r.y = fmaxf((a0.y + a1.y) * inv + z.y + b.y, 0.f);
    r.z = fmaxf((a0.z + a1.z) * inv + z.z + b.z, 0.f);
    r.w = fmaxf((a0.w + a1.w) * inv + z.w + b.w, 0.f);
    g_h[node * 32 + lane] = r;
    if (WRITE_SPLIT) {
        int base = node * 128 + lane * 4;
        __nv_bfloat16 h0, l0, h1, l1, h2, l2, h3, l3;
        split2(r.x, h0, l0);
        split2(r.y, h1, l1);
        split2(r.z, h2, l2);
        split2(r.w, h3, l3);
        *(__nv_bfloat162*)(g_Ah + base)     = __nv_bfloat162(h0, h1);
        *(__nv_bfloat162*)(g_Ah + base + 2) = __nv_bfloat162(h2, h3);
        *(__nv_bfloat162*)(g_Al + base)     = __nv_bfloat162(l0, l1);
        *(__nv_bfloat162*)(g_Al + base + 2) = __nv_bfloat162(l2, l3);
    }
}

// ---------------- layer-2 projection: y2 = h@W_l2, z2 = h@W_r2 ---------------
__global__ __launch_bounds__(256) void k_head(const float* __restrict__ Wl,
                                              const float* __restrict__ Wr) {
    int gt = blockIdx.x * blockDim.x + threadIdx.x;
    int node = gt >> 5;
    int lane = gt & 31;
    if (node >= N_NODES) return;
    float4 v = g_h[node * 32 + lane];
    float hv[4] = {v.x, v.y, v.z, v.w};
    float l0 = 0.f, l1 = 0.f, r0 = 0.f, r1 = 0.f;
#pragma unroll
    for (int j = 0; j < 4; j++) {
        int k = lane * 4 + j;
        l0 += hv[j] * __ldg(&Wl[k * 2 + 0]);
        l1 += hv[j] * __ldg(&Wl[k * 2 + 1]);
        r0 += hv[j] * __ldg(&Wr[k * 2 + 0]);
        r1 += hv[j] * __ldg(&Wr[k * 2 + 1]);
    }
#pragma unroll
    for (int off = 16; off; off >>= 1) {
        l0 += __shfl_xor_sync(0xffffffffu, l0, off);
        l1 += __shfl_xor_sync(0xffffffffu, l1, off);
        r0 += __shfl_xor_sync(0xffffffffu, r0, off);
        r1 += __shfl_xor_sync(0xffffffffu, r1, off);
    }
    if (lane == 0) {
        g_y2[node] = make_float2(l0, l1);
        g_z2[node] = make_float2(r0, r1);
    }
}

// ---------------- fused layer-2 gather + finalize -> out ----------------------
// warp per node, lanes strided over edges, shfl reduce.
__global__ __launch_bounds__(256) void k_gather2(const float* __restrict__ bias,
                                                 float* __restrict__ out) {
    int gt = blockIdx.x * blockDim.x + threadIdx.x;
    int node = gt >> 5;
    int lane = gt & 31;
    if (node >= N_NODES) return;
    int beg = g_rowstart[node];
    int end = g_rowstart[node + 1];
    float ax = 0.f, ay = 0.f;
    for (int e = beg + lane; e < end; e += 32) {
        float2 v = g_y2[g_csr[e]];
        ax += v.x;
        ay += v.y;
    }
#pragma unroll
    for (int off = 16; off; off >>= 1) {
        ax += __shfl_xor_sync(0xffffffffu, ax, off);
        ay += __shfl_xor_sync(0xffffffffu, ay, off);
    }
    if (lane == 0) {
        float inv = 1.0f / fmaxf((float)(end - beg), 1.0f);
        float2 z = g_z2[node];
        out[node * 2 + 0] = ax * inv + z.x + bias[0];
        out[node * 2 + 1] = ay * inv + z.y + bias[1];
    }
}

// ---------------- launch ------------------------------------------------------
extern "C" void kernel_launch(void* const* d_in, const int* in_sizes, int n_in,
                              void* d_out, int out_size) {
    const float* x    = (const float*)d_in[0];
    const int*   ei   = (const int*)d_in[1];     // int32 (JAX x64 disabled)
    const float* Wl0  = (const float*)d_in[2];
    const float* bl0  = (const float*)d_in[3];
    const float* Wr0  = (const float*)d_in[4];
    const float* Wl1  = (const float*)d_in[5];
    const float* bl1  = (const float*)d_in[6];
    const float* Wr1  = (const float*)d_in[7];
    const float* Wl2  = (const float*)d_in[8];
    const float* bl2  = (const float*)d_in[9];
    const float* Wr2  = (const float*)d_in[10];
    float*       out  = (float*)d_out;

    const int M = N_NODES;
    dim3 gemm_grid((M + 127) / 128, 2);
    const int WARP_NODES = (N_NODES * 32 + 255) / 256;

    // ---- CSR build ----
    k_zero_degi<<<NB, 256>>>();
    k_hist<<<(N_EDGES + 255) / 256, 256>>>(ei);
    k_scan_block<<<NB, 256>>>();
    k_scan_top<<<1, 512>>>();
    k_scan_fin<<<NB, 256>>>();
    k_fill<<<(N_EDGES + 255) / 256, 256>>>(ei);

    // ---- layer 0 ----
    k_split_x<<<(N_NODES * (KPAD0 / 4) + 255) / 256, 256>>>(x);
    k_split_w<<<(256 * KPAD0 + 255) / 256, 256>>>(Wl0, Wr0, IN_CH, KPAD0);
    tc_gemm<KPAD0><<<gemm_grid, 256>>>(M);
    k_gather128<true><<<WARP_NODES, 256>>>(bl0);

    // ---- layer 1 ----
    k_split_w<<<(256 * HID + 255) / 256, 256>>>(Wl1, Wr1, HID, HID);
    tc_gemm<HID><<<gemm_grid, 256>>>(M);
    k_gather128<false><<<WARP_NODES, 256>>>(bl1);

    // ---- layer 2 ----
    k_head<<<WARP_NODES, 256>>>(Wl2, Wr2);
    k_gather2<<<WARP_NODES, 256>>>(bl2, out);
}

// round 6
// speedup vs baseline: 2.5959x; 1.2143x over previous
#include <cuda_runtime.h>
#include <cuda_bf16.h>
#include <cstdint>

#define N_NODES 100000
#define N_EDGES 1000000
#define IN_CH 166
#define HID 128
#define KPAD0 192
#define SMS 40      // smem row stride in bf16 (80B, conflict-free ldmatrix, 16B multiple)
#define NB ((N_NODES + 255) / 256)

// ---------------- scratch ------------------------------------------------------
__device__ float4 g_y[N_NODES * (HID / 4)];
__device__ float4 g_z[N_NODES * (HID / 4)];
__device__ float4 g_h[N_NODES * (HID / 4)];
__device__ float2 g_y2[N_NODES];
__device__ float2 g_z2[N_NODES];
__device__ int g_degi[N_NODES];
__device__ int g_lex[N_NODES];
__device__ int g_bsum[NB];
__device__ int g_boff[NB];
__device__ int g_rowstart[N_NODES + 1];
__device__ int g_cursor[N_NODES];
__device__ int g_csr[N_EDGES];
__device__ __nv_bfloat16 g_Ah[N_NODES * KPAD0];
__device__ __nv_bfloat16 g_Al[N_NODES * KPAD0];
__device__ __nv_bfloat16 g_Bh[256 * KPAD0];     // layer-0 weights (Wl|Wr)
__device__ __nv_bfloat16 g_Bl[256 * KPAD0];
__device__ __nv_bfloat16 g_Bh2[256 * HID];      // layer-1 weights
__device__ __nv_bfloat16 g_Bl2[256 * HID];

// ---------------- helpers ------------------------------------------------------
__device__ __forceinline__ uint32_t smem_u32(const void* p) {
    return (uint32_t)__cvta_generic_to_shared(p);
}
__device__ __forceinline__ void ldsm_x4(uint32_t& r0, uint32_t& r1, uint32_t& r2,
                                        uint32_t& r3, uint32_t addr) {
    asm volatile("ldmatrix.sync.aligned.m8n8.x4.shared.b16 {%0,%1,%2,%3}, [%4];"
                 : "=r"(r0), "=r"(r1), "=r"(r2), "=r"(r3) : "r"(addr));
}
__device__ __forceinline__ void mma_bf16(float* d, const uint32_t* a, uint32_t b0, uint32_t b1) {
    asm volatile(
        "mma.sync.aligned.m16n8k16.row.col.f32.bf16.bf16.f32 "
        "{%0,%1,%2,%3}, {%4,%5,%6,%7}, {%8,%9}, {%0,%1,%2,%3};"
        : "+f"(d[0]), "+f"(d[1]), "+f"(d[2]), "+f"(d[3])
        : "r"(a[0]), "r"(a[1]), "r"(a[2]), "r"(a[3]), "r"(b0), "r"(b1));
}
__device__ __forceinline__ void split2(float v, __nv_bfloat16& hi, __nv_bfloat16& lo) {
    hi = __float2bfloat16(v);
    lo = __float2bfloat16(v - __bfloat162float(hi));
}
__device__ __forceinline__ void cp16z(uint32_t dst, const void* src, int vsz) {
    asm volatile("cp.async.ca.shared.global [%0], [%1], 16, %2;"
                 :: "r"(dst), "l"(src), "r"(vsz));
}
__device__ __forceinline__ void cp_commit() {
    asm volatile("cp.async.commit_group;");
}
template <int N>
__device__ __forceinline__ void cp_wait() {
    asm volatile("cp.async.wait_group %0;" :: "n"(N));
}

// ---------------- CSR build ----------------------------------------------------
__global__ __launch_bounds__(256) void k_zero_degi() {
    int i = blockIdx.x * blockDim.x + threadIdx.x;
    if (i < N_NODES) g_degi[i] = 0;
}
__global__ __launch_bounds__(256) void k_hist(const int* __restrict__ ei) {
    int e = blockIdx.x * blockDim.x + threadIdx.x;
    if (e >= N_EDGES) return;
    atomicAdd(&g_degi[ei[N_EDGES + e]], 1);
}
__global__ __launch_bounds__(256) void k_scan_block() {
    __shared__ int s[256];
    int i = blockIdx.x * 256 + threadIdx.x;
    int t = threadIdx.x;
    int v = (i < N_NODES) ? g_degi[i] : 0;
    s[t] = v;
    __syncthreads();
#pragma unroll
    for (int off = 1; off < 256; off <<= 1) {
        int add = (t >= off) ? s[t - off] : 0;
        __syncthreads();
        s[t] += add;
        __syncthreads();
    }
    if (i < N_NODES) g_lex[i] = s[t] - v;
    if (t == 255) g_bsum[blockIdx.x] = s[255];
}
__global__ __launch_bounds__(512) void k_scan_top() {
    __shared__ int s[512];
    int t = threadIdx.x;
    int v = (t < NB) ? g_bsum[t] : 0;
    s[t] = v;
    __syncthreads();
#pragma unroll
    for (int off = 1; off < 512; off <<= 1) {
        int add = (t >= off) ? s[t - off] : 0;
        __syncthreads();
        s[t] += add;
        __syncthreads();
    }
    if (t < NB) g_boff[t] = s[t] - v;
}
__global__ __launch_bounds__(256) void k_scan_fin() {
    int i = blockIdx.x * 256 + threadIdx.x;
    if (i < N_NODES) {
        int rs = g_lex[i] + g_boff[blockIdx.x];
        g_rowstart[i] = rs;
        g_cursor[i] = rs;
    }
    if (i == 0) g_rowstart[N_NODES] = N_EDGES;
}
__global__ __launch_bounds__(256) void k_fill(const int* __restrict__ ei) {
    int e = blockIdx.x * blockDim.x + threadIdx.x;
    if (e >= N_EDGES) return;
    int s = ei[e];
    int d = ei[N_EDGES + e];
    int pos = atomicAdd(&g_cursor[d], 1);
    g_csr[pos] = s;
}

// ---------------- split passes -------------------------------------------------
__global__ __launch_bounds__(256) void k_split_x(const float* __restrict__ x) {
    int i = blockIdx.x * blockDim.x + threadIdx.x;
    if (i >= N_NODES * (KPAD0 / 4)) return;
    int m = i / (KPAD0 / 4);
    int c = (i - m * (KPAD0 / 4)) * 4;
    __nv_bfloat16 hi[4], lo[4];
#pragma unroll
    for (int j = 0; j < 4; j++) {
        float v = (c + j < IN_CH) ? __ldg(&x[(size_t)m * IN_CH + c + j]) : 0.f;
        split2(v, hi[j], lo[j]);
    }
    size_t o = (size_t)m * KPAD0 + c;
    *(__nv_bfloat162*)(g_Ah + o)     = __nv_bfloat162(hi[0], hi[1]);
    *(__nv_bfloat162*)(g_Ah + o + 2) = __nv_bfloat162(hi[2], hi[3]);
    *(__nv_bfloat162*)(g_Al + o)     = __nv_bfloat162(lo[0], lo[1]);
    *(__nv_bfloat162*)(g_Al + o + 2) = __nv_bfloat162(lo[2], lo[3]);
}

// which=0 -> g_Bh/g_Bl (layer 0), which=1 -> g_Bh2/g_Bl2 (layer 1)
__global__ __launch_bounds__(256) void k_split_w(const float* __restrict__ Wl,
                                                 const float* __restrict__ Wr,
                                                 int K, int KP, int which) {
    int i = blockIdx.x * blockDim.x + threadIdx.x;
    if (i >= 256 * KP) return;
    int n = i / KP, k = i - n * KP;
    float v = 0.f;
    if (k < K) v = (n < 128) ? Wl[k * 128 + n] : Wr[k * 128 + (n - 128)];
    __nv_bfloat16 hi, lo;
    split2(v, hi, lo);
    if (which == 0) { g_Bh[i] = hi; g_Bl[i] = lo; }
    else            { g_Bh2[i] = hi; g_Bl2[i] = lo; }
}

// ---------------- bf16x3 tensor-core GEMM, cp.async double-buffered -----------
// blockIdx.y: 0 -> Wl half -> g_y ; 1 -> Wr half -> g_z.
// dynamic smem: 2 stages x 4 tiles x (128*SMS) bf16 = 81920 B
#define TILE_E (128 * SMS)
template <int KPAD>
__global__ __launch_bounds__(256) void tc_gemm(int M, int wsel) {
    extern __shared__ __nv_bfloat16 sm[];
    const int tid = threadIdx.x;
    const int lane = tid & 31;
    const int wid = tid >> 5;
    const int warpM = wid >> 1;
    const int warpN = wid & 1;
    const int m0 = blockIdx.x * 128;
    const int by = blockIdx.y;
    const int NK = KPAD / 32;

    const __nv_bfloat16* __restrict__ Bgh = (wsel ? g_Bh2 : g_Bh) + by * 128 * KPAD;
    const __nv_bfloat16* __restrict__ Bgl = (wsel ? g_Bl2 : g_Bl) + by * 128 * KPAD;

    const int srow = tid >> 1;
    const int shalf = (tid & 1) * 16;
    const int so = srow * SMS + shalf;
    const int avsz = (m0 + srow < M) ? 16 : 0;
    const size_t arow = (size_t)(m0 + srow) * KPAD + shalf;
    const size_t brow = (size_t)srow * KPAD + shalf;

    // stage loader: copies 2x16B per tile per thread
    auto load_stage = [&](int s, int k0) {
        __nv_bfloat16* base = sm + s * 4 * TILE_E;
        uint32_t dAh = smem_u32(base + so);
        uint32_t dAl = smem_u32(base + TILE_E + so);
        uint32_t dBh = smem_u32(base + 2 * TILE_E + so);
        uint32_t dBl = smem_u32(base + 3 * TILE_E + so);
        cp16z(dAh,      g_Ah + arow + k0, avsz);
        cp16z(dAh + 16, g_Ah + arow + k0 + 8, avsz);
        cp16z(dAl,      g_Al + arow + k0, avsz);
        cp16z(dAl + 16, g_Al + arow + k0 + 8, avsz);
        cp16z(dBh,      Bgh + brow + k0, 16);
        cp16z(dBh + 16, Bgh + brow + k0 + 8, 16);
        cp16z(dBl,      Bgl + brow + k0, 16);
        cp16z(dBl + 16, Bgl + brow + k0 + 8, 16);
    };

    float acc[2][8][4];
#pragma unroll
    for (int a = 0; a < 2; a++)
#pragma unroll
        for (int b = 0; b < 8; b++)
#pragma unroll
            for (int c = 0; c < 4; c++) acc[a][b][c] = 0.f;

    load_stage(0, 0);
    cp_commit();

    for (int it = 0; it < NK; it++) {
        if (it + 1 < NK) {
            load_stage((it + 1) & 1, (it + 1) * 32);
            cp_commit();
            cp_wait<1>();
        } else {
            cp_wait<0>();
        }
        __syncthreads();

        __nv_bfloat16* base = sm + (it & 1) * 4 * TILE_E;
        __nv_bfloat16* Ah_s = base;
        __nv_bfloat16* Al_s = base + TILE_E;
        __nv_bfloat16* Bh_s = base + 2 * TILE_E;
        __nv_bfloat16* Bl_s = base + 3 * TILE_E;

#pragma unroll
        for (int kk = 0; kk < 32; kk += 16) {
            uint32_t ah[2][4], al[2][4];
#pragma unroll
            for (int mt = 0; mt < 2; mt++) {
                int r = warpM * 32 + mt * 16 + (lane & 15);
                int c = kk + ((lane >> 4) << 3);
                ldsm_x4(ah[mt][0], ah[mt][1], ah[mt][2], ah[mt][3],
                        smem_u32(Ah_s + r * SMS + c));
                ldsm_x4(al[mt][0], al[mt][1], al[mt][2], al[mt][3],
                        smem_u32(Al_s + r * SMS + c));
            }
#pragma unroll
            for (int g = 0; g < 4; g++) {
                int nrow = warpN * 64 + g * 16 + (lane & 7) + ((lane >> 4) << 3);
                int kc = kk + (((lane >> 3) & 1) << 3);
                uint32_t bh0, bh1, bh2, bh3, bl0, bl1, bl2, bl3;
                ldsm_x4(bh0, bh1, bh2, bh3, smem_u32(Bh_s + nrow * SMS + kc));
                ldsm_x4(bl0, bl1, bl2, bl3, smem_u32(Bl_s + nrow * SMS + kc));
#pragma unroll
                for (int mt = 0; mt < 2; mt++) {
                    mma_bf16(acc[mt][g * 2],     ah[mt], bh0, bh1);
                    mma_bf16(acc[mt][g * 2],     ah[mt], bl0, bl1);
                    mma_bf16(acc[mt][g * 2],     al[mt], bh0, bh1);
                    mma_bf16(acc[mt][g * 2 + 1], ah[mt], bh2, bh3);
                    mma_bf16(acc[mt][g * 2 + 1], ah[mt], bl2, bl3);
                    mma_bf16(acc[mt][g * 2 + 1], al[mt], bh2, bh3);
                }
            }
        }
        __syncthreads();   // stage reusable for prefetch issued next iteration
    }

    float* Cb = (by == 0) ? (float*)g_y : (float*)g_z;
#pragma unroll
    for (int mt = 0; mt < 2; mt++) {
#pragma unroll
        for (int j = 0; j < 8; j++) {
            int row = m0 + warpM * 32 + mt * 16 + (lane >> 2);
            int col = warpN * 64 + j * 8 + 2 * (lane & 3);
            if (row < M)
                *(float2*)((float*)Cb + (size_t)row * 128 + col) =
                    make_float2(acc[mt][j][0], acc[mt][j][1]);
            if (row + 8 < M)
                *(float2*)((float*)Cb + (size_t)(row + 8) * 128 + col) =
                    make_float2(acc[mt][j][2], acc[mt][j][3]);
        }
    }
}

// ---------------- fused CSR gather + mean + self + bias + relu (+head) --------
template <bool WRITE_SPLIT, bool HEAD>
__global__ __launch_bounds__(256) void k_gather128(const float* __restrict__ bias,
                                                   const float* __restrict__ Wl2,
                                                   const float* __restrict__ Wr2) {
    int gt = blockIdx.x * blockDim.x + threadIdx.x;
    int node = gt >> 5;
    int lane = gt & 31;
    if (node >= N_NODES) return;
    int beg = g_rowstart[node];
    int end = g_rowstart[node + 1];
    float4 a0 = make_float4(0.f, 0.f, 0.f, 0.f);
    float4 a1 = make_float4(0.f, 0.f, 0.f, 0.f);
    int e = beg;
    for (; e + 1 < end; e += 2) {
        int s0 = g_csr[e], s1 = g_csr[e + 1];
        float4 v0 = g_y[s0 * 32 + lane];
        float4 v1 = g_y[s1 * 32 + lane];
        a0.x += v0.x; a0.y += v0.y; a0.z += v0.z; a0.w += v0.w;
        a1.x += v1.x; a1.y += v1.y; a1.z += v1.z; a1.w += v1.w;
    }
    if (e < end) {
        float4 v0 = g_y[g_csr[e] * 32 + lane];
        a0.x += v0.x; a0.y += v0.y; a0.z += v0.z; a0.w += v0.w;
    }
    float inv = 1.0f / fmaxf((float)(end - beg), 1.0f);
    float4 z = g_z[node * 32 + lane];
    float4 b = ((const float4*)bias)[lane];
    float4 r;
    r.x = fmaxf((a0.x + a1.x) * inv + z.x + b.x, 0.f);
    r.y = fmaxf((a0.y + a1.y) * inv + z.y + b.y, 0.f);
    r.z = fmaxf((a0.z + a1.z) * inv + z.z + b.z, 0.f);
    r.w = fmaxf((a0.w + a1.w) * inv + z.w + b.w, 0.f);
    if (!HEAD) g_h[node * 32 + lane] = r;
    if (WRITE_SPLIT) {
        int base = node * 128 + lane * 4;
        __nv_bfloat16 h0, l0, h1, l1, h2, l2, h3, l3;
        split2(r.x, h0, l0);
        split2(r.y, h1, l1);
        split2(r.z, h2, l2);
        split2(r.w, h3, l3);
        *(__nv_bfloat162*)(g_Ah + base)     = __nv_bfloat162(h0, h1);
        *(__nv_bfloat162*)(g_Ah + base + 2) = __nv_bfloat162(h2, h3);
        *(__nv_bfloat162*)(g_Al + base)     = __nv_bfloat162(l0, l1);
        *(__nv_bfloat162*)(g_Al + base + 2) = __nv_bfloat162(l2, l3);
    }
    if (HEAD) {
        // y2/z2 = h @ Wl2 / h @ Wr2 computed in-register (h is in this warp)
        float hv[4] = {r.x, r.y, r.z, r.w};
        float l0 = 0.f, l1 = 0.f, r0 = 0.f, r1 = 0.f;
#pragma unroll
        for (int j = 0; j < 4; j++) {
            int k = lane * 4 + j;
            l0 += hv[j] * __ldg(&Wl2[k * 2 + 0]);
            l1 += hv[j] * __ldg(&Wl2[k * 2 + 1]);
            r0 += hv[j] * __ldg(&Wr2[k * 2 + 0]);
            r1 += hv[j] * __ldg(&Wr2[k * 2 + 1]);
        }
#pragma unroll
        for (int off = 16; off; off >>= 1) {
            l0 += __shfl_xor_sync(0xffffffffu, l0, off);
            l1 += __shfl_xor_sync(0xffffffffu, l1, off);
            r0 += __shfl_xor_sync(0xffffffffu, r0, off);
            r1 += __shfl_xor_sync(0xffffffffu, r1, off);
        }
        if (lane == 0) {
            g_y2[node] = make_float2(l0, l1);
            g_z2[node] = make_float2(r0, r1);
        }
    }
}

// ---------------- fused layer-2 gather + finalize -> out ----------------------
__global__ __launch_bounds__(256) void k_gather2(const float* __restrict__ bias,
                                                 float* __restrict__ out) {
    int gt = blockIdx.x * blockDim.x + threadIdx.x;
    int node = gt >> 5;
    int lane = gt & 31;
    if (node >= N_NODES) return;
    int beg = g_rowstart[node];
    int end = g_rowstart[node + 1];
    float ax = 0.f, ay = 0.f;
    for (int e = beg + lane; e < end; e += 32) {
        float2 v = g_y2[g_csr[e]];
        ax += v.x;
        ay += v.y;
    }
#pragma unroll
    for (int off = 16; off; off >>= 1) {
        ax += __shfl_xor_sync(0xffffffffu, ax, off);
        ay += __shfl_xor_sync(0xffffffffu, ay, off);
    }
    if (lane == 0) {
        float inv = 1.0f / fmaxf((float)(end - beg), 1.0f);
        float2 z = g_z2[node];
        out[node * 2 + 0] = ax * inv + z.x + bias[0];
        out[node * 2 + 1] = ay * inv + z.y + bias[1];
    }
}

// ---------------- launch -------------------------------------------------------
extern "C" void kernel_launch(void* const* d_in, const int* in_sizes, int n_in,
                              void* d_out, int out_size) {
    const float* x    = (const float*)d_in[0];
    const int*   ei   = (const int*)d_in[1];     // int32 (JAX x64 disabled)
    const float* Wl0  = (const float*)d_in[2];
    const float* bl0  = (const float*)d_in[3];
    const float* Wr0  = (const float*)d_in[4];
    const float* Wl1  = (const float*)d_in[5];
    const float* bl1  = (const float*)d_in[6];
    const float* Wr1  = (const float*)d_in[7];
    const float* Wl2  = (const float*)d_in[8];
    const float* bl2  = (const float*)d_in[9];
    const float* Wr2  = (const float*)d_in[10];
    float*       out  = (float*)d_out;

    const int M = N_NODES;
    dim3 gemm_grid((M + 127) / 128, 2);
    const int WARP_NODES = (N_NODES * 32 + 255) / 256;
    const int SMEM_BYTES = 2 * 4 * TILE_E * (int)sizeof(__nv_bfloat16);  // 81920

    cudaFuncSetAttribute(tc_gemm<KPAD0>, cudaFuncAttributeMaxDynamicSharedMemorySize, SMEM_BYTES);
    cudaFuncSetAttribute(tc_gemm<HID>,   cudaFuncAttributeMaxDynamicSharedMemorySize, SMEM_BYTES);

    // ---- fork: CSR build + layer-1 weight split on side stream ----
    cudaStream_t s2;
    cudaStreamCreateWithFlags(&s2, cudaStreamNonBlocking);
    cudaEvent_t evRoot, evCsr;
    cudaEventCreateWithFlags(&evRoot, cudaEventDisableTiming);
    cudaEventCreateWithFlags(&evCsr, cudaEventDisableTiming);

    cudaEventRecord(evRoot, 0);
    cudaStreamWaitEvent(s2, evRoot, 0);

    k_zero_degi<<<NB, 256, 0, s2>>>();
    k_hist<<<(N_EDGES + 255) / 256, 256, 0, s2>>>(ei);
    k_scan_block<<<NB, 256, 0, s2>>>();
    k_scan_top<<<1, 512, 0, s2>>>();
    k_scan_fin<<<NB, 256, 0, s2>>>();
    k_fill<<<(N_EDGES + 255) / 256, 256, 0, s2>>>(ei);
    k_split_w<<<(256 * HID + 255) / 256, 256, 0, s2>>>(Wl1, Wr1, HID, HID, 1);
    cudaEventRecord(evCsr, s2);

    // ---- main stream: layer 0 projection ----
    k_split_x<<<(N_NODES * (KPAD0 / 4) + 255) / 256, 256>>>(x);
    k_split_w<<<(256 * KPAD0 + 255) / 256, 256>>>(Wl0, Wr0, IN_CH, KPAD0, 0);
    tc_gemm<KPAD0><<<gemm_grid, 256, SMEM_BYTES>>>(M, 0);

    // ---- join, then aggregation + remaining layers ----
    cudaStreamWaitEvent(0, evCsr, 0);
    k_gather128<true, false><<<WARP_NODES, 256>>>(bl0, nullptr, nullptr);
    tc_gemm<HID><<<gemm_grid, 256, SMEM_BYTES>>>(M, 1);
    k_gather128<false, true><<<WARP_NODES, 256>>>(bl1, Wl2, Wr2);
    k_gather2<<<WARP_NODES, 256>>>(bl2, out);

    cudaEventDestroy(evRoot);
    cudaEventDestroy(evCsr);
    cudaStreamDestroy(s2);
}